// round 7
// baseline (speedup 1.0000x reference)
#include <cuda_runtime.h>
#include <cuda_bf16.h>
#include <cstdint>

#define T_TOKENS 2048
#define DIM_     2048
#define HID_     5632
#define NEXP     8
#define NENT     (T_TOKENS * 2)

// ---------------------------------------------------------------------------
// Scratch (device globals — no cudaMalloc allowed)
// ---------------------------------------------------------------------------
__device__ int   g_eid [T_TOKENS][2];
__device__ float g_ew  [T_TOKENS][2];
__device__ int   g_pos [T_TOKENS][2];
__device__ int   g_list[NEXP][T_TOKENS];
__device__ int   g_cnt [NEXP];
__device__ int   g_off [NEXP];
__device__ __nv_bfloat16 g_xhi[(size_t)T_TOKENS * DIM_];
__device__ __nv_bfloat16 g_xlo[(size_t)T_TOKENS * DIM_];
__device__ __nv_bfloat16 g_hh [(size_t)NENT * HID_];
__device__ __nv_bfloat16 g_hl [(size_t)NENT * HID_];
__device__ float         g_y  [(size_t)NENT * DIM_];
// Pre-split, pre-transposed weights (bf16 hi/lo), GEMM-B layout:
// g_b1*: [E][2*HID rows][DIM k], row 2j = w1 col j, row 2j+1 = w3 col j
// g_b2*: [E][DIM rows][HID k]
__device__ __nv_bfloat16 g_b1h[(size_t)NEXP * 2 * HID_ * DIM_];
__device__ __nv_bfloat16 g_b1l[(size_t)NEXP * 2 * HID_ * DIM_];
__device__ __nv_bfloat16 g_b2h[(size_t)NEXP * DIM_ * HID_];
__device__ __nv_bfloat16 g_b2l[(size_t)NEXP * DIM_ * HID_];

// ---------------------------------------------------------------------------
// Helpers
// ---------------------------------------------------------------------------
__device__ __forceinline__ uint32_t smem_u32(const void* p) {
    uint32_t a;
    asm("{ .reg .u64 t; cvta.to.shared.u64 t, %1; cvt.u32.u64 %0, t; }" : "=r"(a) : "l"(p));
    return a;
}
__device__ __forceinline__ uint32_t pkbf(__nv_bfloat16 a, __nv_bfloat16 b) {
    return (uint32_t)__bfloat16_as_ushort(a) | ((uint32_t)__bfloat16_as_ushort(b) << 16);
}
__device__ __forceinline__ void split_pair(float f0, float f1, uint32_t& hp, uint32_t& lp) {
    __nv_bfloat16 h0 = __float2bfloat16(f0);
    __nv_bfloat16 h1 = __float2bfloat16(f1);
    __nv_bfloat16 l0 = __float2bfloat16(f0 - __bfloat162float(h0));
    __nv_bfloat16 l1 = __float2bfloat16(f1 - __bfloat162float(h1));
    hp = pkbf(h0, h1);
    lp = pkbf(l0, l1);
}

#define LDM_X4(r, addr)                                                          \
    asm volatile("ldmatrix.sync.aligned.m8n8.x4.shared.b16 {%0,%1,%2,%3}, [%4];" \
        : "=r"((r)[0]), "=r"((r)[1]), "=r"((r)[2]), "=r"((r)[3]) : "r"(addr))

#define MMA_BF16(d, a, b0, b1)                                                   \
    asm volatile("mma.sync.aligned.m16n8k16.row.col.f32.bf16.bf16.f32 "          \
        "{%0,%1,%2,%3}, {%4,%5,%6,%7}, {%8,%9}, {%0,%1,%2,%3};"                  \
        : "+f"((d)[0]), "+f"((d)[1]), "+f"((d)[2]), "+f"((d)[3])                 \
        : "r"((a)[0]), "r"((a)[1]), "r"((a)[2]), "r"((a)[3]), "r"(b0), "r"(b1))

#define CP_ASYNC16(dst, src)                                                     \
    asm volatile("cp.async.cg.shared.global [%0], [%1], 16;" :: "r"(dst), "l"(src))
#define CP_COMMIT() asm volatile("cp.async.commit_group;" ::: "memory")
#define CP_WAIT0()  asm volatile("cp.async.wait_group 0;" ::: "memory")

// Smem geometry: rows of 32 bf16 padded to 80B -> conflict-free ldmatrix.
#define ROWB    80
#define TILE_A  10240           // 128 rows * 80B (one A matrix: hi or lo)
#define OFF_AH  0
#define OFF_AL  10240
#define OFF_BH  20480
#define OFF_BL  25600
#define STAGE_B 30720
#define SMEM_TOT (2 * STAGE_B)  // 61440; 3 CTAs/SM

// ---------------------------------------------------------------------------
// Gating + routing + x split
// ---------------------------------------------------------------------------
__global__ void gate_kernel(const float* __restrict__ x, const float* __restrict__ gw) {
    const int t = blockIdx.x, lane = threadIdx.x & 31, w = threadIdx.x >> 5;
    const float* xr = x + (size_t)t * DIM_;
    const float* gr = gw + (size_t)w * DIM_;
    float s = 0.f;
    for (int d = lane * 4; d < DIM_; d += 128) {
        float4 a = *(const float4*)(xr + d);
        float4 b = *(const float4*)(gr + d);
        s += a.x * b.x + a.y * b.y + a.z * b.z + a.w * b.w;
    }
    #pragma unroll
    for (int o = 16; o; o >>= 1) s += __shfl_xor_sync(0xffffffffu, s, o);
    __shared__ float sc[NEXP];
    if (lane == 0) sc[w] = s;
    __syncthreads();
    if (threadIdx.x == 0) {
        int b0 = 0; float s0 = sc[0];
        #pragma unroll
        for (int e = 1; e < NEXP; e++) if (sc[e] > s0) { s0 = sc[e]; b0 = e; }
        int b1 = -1; float s1 = -1e30f;
        #pragma unroll
        for (int e = 0; e < NEXP; e++) if (e != b0 && sc[e] > s1) { s1 = sc[e]; b1 = e; }
        float e1 = __expf(s1 - s0);
        float inv = 1.f / (1.f + e1);
        g_eid[t][0] = b0; g_eid[t][1] = b1;
        g_ew [t][0] = inv; g_ew [t][1] = e1 * inv;
    }
}

__global__ void route_kernel() {
    const int lane = threadIdx.x & 31, e = threadIdx.x >> 5;
    if (e < NEXP) {
        int cnt = 0;
        for (int t0 = 0; t0 < T_TOKENS; t0 += 32) {
            int t = t0 + lane;
            int e0 = g_eid[t][0], e1 = g_eid[t][1];
            bool sel = (e0 == e) || (e1 == e);
            int slot = (e0 == e) ? 0 : 1;
            unsigned m = __ballot_sync(0xffffffffu, sel);
            if (sel) {
                int p = cnt + __popc(m & ((1u << lane) - 1u));
                g_list[e][p] = t;
                g_pos[t][slot] = p;
            }
            cnt += __popc(m);
        }
        if (lane == 0) g_cnt[e] = cnt;
    }
    __syncthreads();
    if (threadIdx.x == 0) {
        int off = 0;
        #pragma unroll
        for (int i = 0; i < NEXP; i++) { g_off[i] = off; off += g_cnt[i]; }
    }
}

__global__ void split_x_kernel(const float* __restrict__ x) {
    int i = blockIdx.x * blockDim.x + threadIdx.x;
    float4 v = ((const float4*)x)[i];
    size_t o = (size_t)i * 4;
    float vv[4] = {v.x, v.y, v.z, v.w};
    #pragma unroll
    for (int k = 0; k < 4; k++) {
        __nv_bfloat16 h = __float2bfloat16(vv[k]);
        g_xhi[o + k] = h;
        g_xlo[o + k] = __float2bfloat16(vv[k] - __bfloat162float(h));
    }
}

// ---------------------------------------------------------------------------
// Pre-pass 1: split+transpose w1/w3 [E][DIM k][HID n] -> g_b1h/l [E][2n][k]
// interleaved rows (2j = w1 col j, 2j+1 = w3 col j).  Tile 64k x 32n.
// ---------------------------------------------------------------------------
__global__ void __launch_bounds__(256) split_w13_kernel(const float* __restrict__ w1,
                                                        const float* __restrict__ w3) {
    __shared__ float t1[64][33];
    __shared__ float t3[64][33];
    const int e = blockIdx.z, k0 = blockIdx.x * 64, n0 = blockIdx.y * 32;
    const int tx = threadIdx.x & 31, ty = threadIdx.x >> 5;
    const float* p1 = w1 + ((size_t)e * DIM_ + k0) * HID_ + n0;
    const float* p3 = w3 + ((size_t)e * DIM_ + k0) * HID_ + n0;
    #pragma unroll
    for (int j = 0; j < 8; j++) {
        int r = ty + 8 * j;
        t1[r][tx] = p1[(size_t)r * HID_ + tx];
        t3[r][tx] = p3[(size_t)r * HID_ + tx];
    }
    __syncthreads();
    #pragma unroll
    for (int j = 0; j < 4; j++) {
        int n = ty + 8 * j;
        uint32_t hp, lp;
        size_t r1 = ((size_t)e * (2 * HID_) + 2 * (n0 + n)) * DIM_ + k0;
        split_pair(t1[2 * tx][n], t1[2 * tx + 1][n], hp, lp);
        ((uint32_t*)(g_b1h + r1))[tx] = hp;
        ((uint32_t*)(g_b1l + r1))[tx] = lp;
        split_pair(t3[2 * tx][n], t3[2 * tx + 1][n], hp, lp);
        ((uint32_t*)(g_b1h + r1 + DIM_))[tx] = hp;
        ((uint32_t*)(g_b1l + r1 + DIM_))[tx] = lp;
    }
}

// ---------------------------------------------------------------------------
// Pre-pass 2: split+transpose w2 [E][HID k][DIM n] -> g_b2h/l [E][n][k]
// ---------------------------------------------------------------------------
__global__ void __launch_bounds__(256) split_w2_kernel(const float* __restrict__ w2) {
    __shared__ float t2[64][33];
    const int e = blockIdx.z, k0 = blockIdx.x * 64, n0 = blockIdx.y * 32;
    const int tx = threadIdx.x & 31, ty = threadIdx.x >> 5;
    const float* p2 = w2 + ((size_t)e * HID_ + k0) * DIM_ + n0;
    #pragma unroll
    for (int j = 0; j < 8; j++) {
        int r = ty + 8 * j;
        t2[r][tx] = p2[(size_t)r * DIM_ + tx];
    }
    __syncthreads();
    #pragma unroll
    for (int j = 0; j < 4; j++) {
        int n = ty + 8 * j;
        uint32_t hp, lp;
        split_pair(t2[2 * tx][n], t2[2 * tx + 1][n], hp, lp);
        size_t ro = ((size_t)e * DIM_ + n0 + n) * HID_ + k0;
        ((uint32_t*)(g_b2h + ro))[tx] = hp;
        ((uint32_t*)(g_b2l + ro))[tx] = lp;
    }
}

// ---------------------------------------------------------------------------
// GEMM1: u = x@w1, v = x@w3 (3-term bf16 split), h = silu(u)*v
// 128 threads = 4 warps (2m x 2n), warp tile 64x32. CTA: 128 tokens x 32 h-cols.
// A AND B via cp.async from pre-split bf16 globals. Zero in-loop conversion.
// ---------------------------------------------------------------------------
__global__ void __launch_bounds__(128, 3) ffn1_kernel() {
    const int e   = blockIdx.z;
    const int cnt = g_cnt[e];
    const int m0  = blockIdx.x * 128;
    if (m0 >= cnt) return;
    const int n0   = blockIdx.y * 32;     // h-cols
    const int base = g_off[e];

    extern __shared__ char sm[];
    const uint32_t sbase = smem_u32(sm);
    const int tid = threadIdx.x, lane = tid & 31, wid = tid >> 5;
    const int wm = wid & 1, wn = wid >> 1;

    // A loader: 1024 cp.async tasks (2 mats x 128 rows x 4 kq), 8/thread
    const __nv_bfloat16* apA[8];
    uint32_t aoA[8];
    #pragma unroll
    for (int q = 0; q < 8; q++) {
        int idx = tid + q * 128;
        int mat = idx >> 9;
        int rem = idx & 511;
        int row = rem >> 2, kq = rem & 3;
        int tok = g_list[e][min(m0 + row, cnt - 1)];
        apA[q] = (mat ? g_xlo : g_xhi) + (size_t)tok * DIM_ + kq * 8;
        aoA[q] = mat * TILE_A + row * ROWB + kq * 16;
    }
    // B loader: 512 cp.async tasks (2 mats x 64 rows x 4 kq), 4/thread
    const __nv_bfloat16* apB[4];
    uint32_t aoB[4];
    #pragma unroll
    for (int q = 0; q < 4; q++) {
        int idx = tid + q * 128;
        int mat = idx >> 8;
        int rem = idx & 255;
        int row = rem >> 2, kq = rem & 3;
        apB[q] = (mat ? g_b1l : g_b1h)
               + ((size_t)e * (2 * HID_) + 2 * n0 + row) * DIM_ + kq * 8;
        aoB[q] = (mat ? OFF_BL : OFF_BH) + row * ROWB + kq * 16;
    }

    const int mi = lane >> 3, lr = lane & 7;
    const uint32_t aLB = (uint32_t)((wm * 64 + (mi & 1) * 8 + lr) * ROWB + (mi >> 1) * 16);
    const uint32_t bLB = (uint32_t)((wn * 32 + (mi >> 1) * 8 + lr) * ROWB + (mi & 1) * 16);

    float acc[4][4][4];
    #pragma unroll
    for (int a = 0; a < 4; a++)
        #pragma unroll
        for (int b = 0; b < 4; b++)
            #pragma unroll
            for (int c = 0; c < 4; c++) acc[a][b][c] = 0.f;

    // prologue: stage 0
    #pragma unroll
    for (int q = 0; q < 8; q++) CP_ASYNC16(sbase + aoA[q], apA[q]);
    #pragma unroll
    for (int q = 0; q < 4; q++) CP_ASYNC16(sbase + aoB[q], apB[q]);
    CP_COMMIT();
    CP_WAIT0();
    __syncthreads();

    const int NCH = DIM_ / 32;   // 64
    for (int i = 0; i < NCH; i++) {
        const uint32_t stS = sbase + (i & 1) * STAGE_B;
        if (i + 1 < NCH) {
            const uint32_t stN = sbase + ((i + 1) & 1) * STAGE_B;
            int k0n = (i + 1) * 32;
            #pragma unroll
            for (int q = 0; q < 8; q++) CP_ASYNC16(stN + aoA[q], apA[q] + k0n);
            #pragma unroll
            for (int q = 0; q < 4; q++) CP_ASYNC16(stN + aoB[q], apB[q] + k0n);
            CP_COMMIT();
        }
        #pragma unroll
        for (int ks = 0; ks < 2; ks++) {
            uint32_t bh[2][4], bl[2][4];
            #pragma unroll
            for (int ng = 0; ng < 2; ng++) {
                LDM_X4(bh[ng], stS + OFF_BH + bLB + ng * (16 * ROWB) + ks * 32);
                LDM_X4(bl[ng], stS + OFF_BL + bLB + ng * (16 * ROWB) + ks * 32);
            }
            #pragma unroll
            for (int mt = 0; mt < 4; mt++) {
                uint32_t ah[4], al[4];
                LDM_X4(ah, stS + OFF_AH + aLB + mt * (16 * ROWB) + ks * 32);
                LDM_X4(al, stS + OFF_AL + aLB + mt * (16 * ROWB) + ks * 32);
                #pragma unroll
                for (int ng = 0; ng < 2; ng++)
                    #pragma unroll
                    for (int h2 = 0; h2 < 2; h2++) {
                        int nt = ng * 2 + h2;
                        MMA_BF16(acc[mt][nt], ah, bh[ng][2*h2], bh[ng][2*h2+1]);
                        MMA_BF16(acc[mt][nt], al, bh[ng][2*h2], bh[ng][2*h2+1]);
                        MMA_BF16(acc[mt][nt], ah, bl[ng][2*h2], bl[ng][2*h2+1]);
                    }
            }
        }
        CP_WAIT0();
        __syncthreads();
    }

    // epilogue: d0=u, d1=v for the same h-col, in-register SwiGLU
    #pragma unroll
    for (int mt = 0; mt < 4; mt++)
        #pragma unroll
        for (int nt = 0; nt < 4; nt++) {
            int j = wn * 16 + nt * 4 + (lane & 3);
            #pragma unroll
            for (int rr = 0; rr < 2; rr++) {
                int r  = wm * 64 + mt * 16 + (lane >> 2) + rr * 8;
                int gm = m0 + r;
                float u = acc[mt][nt][2*rr], v = acc[mt][nt][2*rr+1];
                float h = u / (1.f + __expf(-u)) * v;
                __nv_bfloat16 hh = __float2bfloat16(h);
                __nv_bfloat16 hl = __float2bfloat16(h - __bfloat162float(hh));
                if (gm < cnt) {
                    size_t dst = (size_t)(base + gm) * HID_ + n0 + j;
                    g_hh[dst] = hh;
                    g_hl[dst] = hl;
                }
            }
        }
}

// ---------------------------------------------------------------------------
// GEMM2: y = h @ w2 (3-term split). 128 threads, warp tile 64x32, CTA 128x64.
// ---------------------------------------------------------------------------
__global__ void __launch_bounds__(128, 3) ffn2_kernel() {
    const int e   = blockIdx.z;
    const int cnt = g_cnt[e];
    const int m0  = blockIdx.x * 128;
    if (m0 >= cnt) return;
    const int n0   = blockIdx.y * 64;
    const int base = g_off[e];

    extern __shared__ char sm[];
    const uint32_t sbase = smem_u32(sm);
    const int tid = threadIdx.x, lane = tid & 31, wid = tid >> 5;
    const int wm = wid & 1, wn = wid >> 1;

    const __nv_bfloat16* apA[8];
    uint32_t aoA[8];
    #pragma unroll
    for (int q = 0; q < 8; q++) {
        int idx = tid + q * 128;
        int mat = idx >> 9;
        int rem = idx & 511;
        int row = rem >> 2, kq = rem & 3;
        int r   = base + min(m0 + row, cnt - 1);
        apA[q] = (mat ? g_hl : g_hh) + (size_t)r * HID_ + kq * 8;
        aoA[q] = mat * TILE_A + row * ROWB + kq * 16;
    }
    const __nv_bfloat16* apB[4];
    uint32_t aoB[4];
    #pragma unroll
    for (int q = 0; q < 4; q++) {
        int idx = tid + q * 128;
        int mat = idx >> 8;
        int rem = idx & 255;
        int row = rem >> 2, kq = rem & 3;
        apB[q] = (mat ? g_b2l : g_b2h)
               + ((size_t)e * DIM_ + n0 + row) * HID_ + kq * 8;
        aoB[q] = (mat ? OFF_BL : OFF_BH) + row * ROWB + kq * 16;
    }

    const int mi = lane >> 3, lr = lane & 7;
    const uint32_t aLB = (uint32_t)((wm * 64 + (mi & 1) * 8 + lr) * ROWB + (mi >> 1) * 16);
    const uint32_t bLB = (uint32_t)((wn * 32 + (mi >> 1) * 8 + lr) * ROWB + (mi & 1) * 16);

    float acc[4][4][4];
    #pragma unroll
    for (int a = 0; a < 4; a++)
        #pragma unroll
        for (int b = 0; b < 4; b++)
            #pragma unroll
            for (int c = 0; c < 4; c++) acc[a][b][c] = 0.f;

    #pragma unroll
    for (int q = 0; q < 8; q++) CP_ASYNC16(sbase + aoA[q], apA[q]);
    #pragma unroll
    for (int q = 0; q < 4; q++) CP_ASYNC16(sbase + aoB[q], apB[q]);
    CP_COMMIT();
    CP_WAIT0();
    __syncthreads();

    const int NCH = HID_ / 32;   // 176
    for (int i = 0; i < NCH; i++) {
        const uint32_t stS = sbase + (i & 1) * STAGE_B;
        if (i + 1 < NCH) {
            const uint32_t stN = sbase + ((i + 1) & 1) * STAGE_B;
            int k0n = (i + 1) * 32;
            #pragma unroll
            for (int q = 0; q < 8; q++) CP_ASYNC16(stN + aoA[q], apA[q] + k0n);
            #pragma unroll
            for (int q = 0; q < 4; q++) CP_ASYNC16(stN + aoB[q], apB[q] + k0n);
            CP_COMMIT();
        }
        #pragma unroll
        for (int ks = 0; ks < 2; ks++) {
            uint32_t bh[2][4], bl[2][4];
            #pragma unroll
            for (int ng = 0; ng < 2; ng++) {
                LDM_X4(bh[ng], stS + OFF_BH + bLB + ng * (16 * ROWB) + ks * 32);
                LDM_X4(bl[ng], stS + OFF_BL + bLB + ng * (16 * ROWB) + ks * 32);
            }
            #pragma unroll
            for (int mt = 0; mt < 4; mt++) {
                uint32_t ah[4], al[4];
                LDM_X4(ah, stS + OFF_AH + aLB + mt * (16 * ROWB) + ks * 32);
                LDM_X4(al, stS + OFF_AL + aLB + mt * (16 * ROWB) + ks * 32);
                #pragma unroll
                for (int ng = 0; ng < 2; ng++)
                    #pragma unroll
                    for (int h2 = 0; h2 < 2; h2++) {
                        int nt = ng * 2 + h2;
                        MMA_BF16(acc[mt][nt], ah, bh[ng][2*h2], bh[ng][2*h2+1]);
                        MMA_BF16(acc[mt][nt], al, bh[ng][2*h2], bh[ng][2*h2+1]);
                        MMA_BF16(acc[mt][nt], ah, bl[ng][2*h2], bl[ng][2*h2+1]);
                    }
            }
        }
        CP_WAIT0();
        __syncthreads();
    }

    #pragma unroll
    for (int mt = 0; mt < 4; mt++)
        #pragma unroll
        for (int nt = 0; nt < 4; nt++) {
            int c = wn * 32 + nt * 8 + (lane & 3) * 2;
            #pragma unroll
            for (int rr = 0; rr < 2; rr++) {
                int r  = wm * 64 + mt * 16 + (lane >> 2) + rr * 8;
                int gm = m0 + r;
                if (gm < cnt) {
                    size_t dst = (size_t)(base + gm) * DIM_ + n0 + c;
                    *(float2*)(g_y + dst) = make_float2(acc[mt][nt][2*rr], acc[mt][nt][2*rr+1]);
                }
            }
        }
}

// ---------------------------------------------------------------------------
// Combine
// ---------------------------------------------------------------------------
__global__ void combine_kernel(float* __restrict__ out) {
    const int t  = blockIdx.x;
    const int e0 = g_eid[t][0];
    const int e1 = g_eid[t][1];
    const int n0 = g_off[e0] + g_pos[t][0];
    const int n1 = g_off[e1] + g_pos[t][1];
    const float w0 = g_ew[t][0];
    const float w1 = g_ew[t][1];
    const float* y0 = &g_y[(size_t)n0 * DIM_];
    const float* y1 = &g_y[(size_t)n1 * DIM_];
    float* op = out + (size_t)t * DIM_;
    for (int d = threadIdx.x * 4; d < DIM_; d += blockDim.x * 4) {
        float4 a = *(const float4*)(y0 + d);
        float4 b = *(const float4*)(y1 + d);
        *(float4*)(op + d) = make_float4(w0 * a.x + w1 * b.x, w0 * a.y + w1 * b.y,
                                         w0 * a.z + w1 * b.z, w0 * a.w + w1 * b.w);
    }
}

// ---------------------------------------------------------------------------
// Entry point
// ---------------------------------------------------------------------------
extern "C" void kernel_launch(void* const* d_in, const int* in_sizes, int n_in,
                              void* d_out, int out_size) {
    const float* x  = (const float*)d_in[0];
    const float* gw = (const float*)d_in[1];
    const float* w1 = (const float*)d_in[2];
    const float* w2 = (const float*)d_in[3];
    const float* w3 = (const float*)d_in[4];
    float* out = (float*)d_out;

    cudaFuncSetAttribute(ffn1_kernel, cudaFuncAttributeMaxDynamicSharedMemorySize, SMEM_TOT);
    cudaFuncSetAttribute(ffn2_kernel, cudaFuncAttributeMaxDynamicSharedMemorySize, SMEM_TOT);

    gate_kernel<<<T_TOKENS, 256>>>(x, gw);
    route_kernel<<<1, 256>>>();
    split_x_kernel<<<(T_TOKENS * DIM_ / 4) / 256, 256>>>(x);
    split_w13_kernel<<<dim3(DIM_ / 64, HID_ / 32, NEXP), 256>>>(w1, w3);
    split_w2_kernel<<<dim3(HID_ / 64, DIM_ / 32, NEXP), 256>>>(w2);
    ffn1_kernel<<<dim3(T_TOKENS / 128, HID_ / 32, NEXP), 128, SMEM_TOT>>>();
    ffn2_kernel<<<dim3(T_TOKENS / 128, DIM_ / 64, NEXP), 128, SMEM_TOT>>>();
    combine_kernel<<<T_TOKENS, 256>>>(out);
}

// round 8
// speedup vs baseline: 1.1591x; 1.1591x over previous
#include <cuda_runtime.h>
#include <cuda_bf16.h>
#include <cstdint>

#define T_TOKENS 2048
#define DIM_     2048
#define HID_     5632
#define NEXP     8
#define NENT     (T_TOKENS * 2)

// ---------------------------------------------------------------------------
// Scratch (device globals — no cudaMalloc allowed)
// ---------------------------------------------------------------------------
__device__ int   g_eid [T_TOKENS][2];
__device__ float g_ew  [T_TOKENS][2];
__device__ int   g_pos [T_TOKENS][2];
__device__ int   g_list[NEXP][T_TOKENS];
__device__ int   g_cnt [NEXP];
__device__ int   g_off [NEXP];
__device__ __nv_bfloat16 g_xhi[(size_t)T_TOKENS * DIM_];
__device__ __nv_bfloat16 g_xlo[(size_t)T_TOKENS * DIM_];
__device__ __nv_bfloat16 g_hh [(size_t)NENT * HID_];
__device__ __nv_bfloat16 g_hl [(size_t)NENT * HID_];
__device__ float         g_y  [(size_t)NENT * DIM_];

// ---------------------------------------------------------------------------
// Helpers
// ---------------------------------------------------------------------------
__device__ __forceinline__ uint32_t smem_u32(const void* p) {
    uint32_t a;
    asm("{ .reg .u64 t; cvta.to.shared.u64 t, %1; cvt.u32.u64 %0, t; }" : "=r"(a) : "l"(p));
    return a;
}
__device__ __forceinline__ uint32_t pkbf(__nv_bfloat16 a, __nv_bfloat16 b) {
    return (uint32_t)__bfloat16_as_ushort(a) | ((uint32_t)__bfloat16_as_ushort(b) << 16);
}
__device__ __forceinline__ void split_pair(float f0, float f1, uint32_t& hp, uint32_t& lp) {
    __nv_bfloat16 h0 = __float2bfloat16(f0);
    __nv_bfloat16 h1 = __float2bfloat16(f1);
    __nv_bfloat16 l0 = __float2bfloat16(f0 - __bfloat162float(h0));
    __nv_bfloat16 l1 = __float2bfloat16(f1 - __bfloat162float(h1));
    hp = pkbf(h0, h1);
    lp = pkbf(l0, l1);
}

#define LDM_X4(r, addr)                                                          \
    asm volatile("ldmatrix.sync.aligned.m8n8.x4.shared.b16 {%0,%1,%2,%3}, [%4];" \
        : "=r"((r)[0]), "=r"((r)[1]), "=r"((r)[2]), "=r"((r)[3]) : "r"(addr))

#define MMA_BF16(d, a, b0, b1)                                                   \
    asm volatile("mma.sync.aligned.m16n8k16.row.col.f32.bf16.bf16.f32 "          \
        "{%0,%1,%2,%3}, {%4,%5,%6,%7}, {%8,%9}, {%0,%1,%2,%3};"                  \
        : "+f"((d)[0]), "+f"((d)[1]), "+f"((d)[2]), "+f"((d)[3])                 \
        : "r"((a)[0]), "r"((a)[1]), "r"((a)[2]), "r"((a)[3]), "r"(b0), "r"(b1))

#define CP_ASYNC16(dst, src)                                                     \
    asm volatile("cp.async.cg.shared.global [%0], [%1], 16;" :: "r"(dst), "l"(src))
#define CP_COMMIT() asm volatile("cp.async.commit_group;" ::: "memory")
#define CP_WAIT0()  asm volatile("cp.async.wait_group 0;" ::: "memory")

// Smem geometry: rows of 32 bf16 padded to 80B -> conflict-free ldmatrix.
#define ROWB    80
#define TILE_A  10240           // 128 rows * 80B (one A matrix: hi or lo)
#define OFF_AH  0
#define OFF_AL  10240
#define OFF_BH  20480
#define OFF_BL  25600
#define STAGE_B 30720
#define SMEM_TOT (2 * STAGE_B)  // 61440; 3 CTAs/SM

// ---------------------------------------------------------------------------
// Gating + routing + x split
// ---------------------------------------------------------------------------
__global__ void gate_kernel(const float* __restrict__ x, const float* __restrict__ gw) {
    const int t = blockIdx.x, lane = threadIdx.x & 31, w = threadIdx.x >> 5;
    const float* xr = x + (size_t)t * DIM_;
    const float* gr = gw + (size_t)w * DIM_;
    float s = 0.f;
    for (int d = lane * 4; d < DIM_; d += 128) {
        float4 a = *(const float4*)(xr + d);
        float4 b = *(const float4*)(gr + d);
        s += a.x * b.x + a.y * b.y + a.z * b.z + a.w * b.w;
    }
    #pragma unroll
    for (int o = 16; o; o >>= 1) s += __shfl_xor_sync(0xffffffffu, s, o);
    __shared__ float sc[NEXP];
    if (lane == 0) sc[w] = s;
    __syncthreads();
    if (threadIdx.x == 0) {
        int b0 = 0; float s0 = sc[0];
        #pragma unroll
        for (int e = 1; e < NEXP; e++) if (sc[e] > s0) { s0 = sc[e]; b0 = e; }
        int b1 = -1; float s1 = -1e30f;
        #pragma unroll
        for (int e = 0; e < NEXP; e++) if (e != b0 && sc[e] > s1) { s1 = sc[e]; b1 = e; }
        float e1 = __expf(s1 - s0);
        float inv = 1.f / (1.f + e1);
        g_eid[t][0] = b0; g_eid[t][1] = b1;
        g_ew [t][0] = inv; g_ew [t][1] = e1 * inv;
    }
}

__global__ void route_kernel() {
    const int lane = threadIdx.x & 31, e = threadIdx.x >> 5;
    if (e < NEXP) {
        int cnt = 0;
        for (int t0 = 0; t0 < T_TOKENS; t0 += 32) {
            int t = t0 + lane;
            int e0 = g_eid[t][0], e1 = g_eid[t][1];
            bool sel = (e0 == e) || (e1 == e);
            int slot = (e0 == e) ? 0 : 1;
            unsigned m = __ballot_sync(0xffffffffu, sel);
            if (sel) {
                int p = cnt + __popc(m & ((1u << lane) - 1u));
                g_list[e][p] = t;
                g_pos[t][slot] = p;
            }
            cnt += __popc(m);
        }
        if (lane == 0) g_cnt[e] = cnt;
    }
    __syncthreads();
    if (threadIdx.x == 0) {
        int off = 0;
        #pragma unroll
        for (int i = 0; i < NEXP; i++) { g_off[i] = off; off += g_cnt[i]; }
    }
}

__global__ void split_x_kernel(const float* __restrict__ x) {
    int i = blockIdx.x * blockDim.x + threadIdx.x;
    float4 v = ((const float4*)x)[i];
    size_t o = (size_t)i * 4;
    float vv[4] = {v.x, v.y, v.z, v.w};
    #pragma unroll
    for (int k = 0; k < 4; k++) {
        __nv_bfloat16 h = __float2bfloat16(vv[k]);
        g_xhi[o + k] = h;
        g_xlo[o + k] = __float2bfloat16(vv[k] - __bfloat162float(h));
    }
}

// ---------------------------------------------------------------------------
// GEMM1: u = x@w1, v = x@w3 (3-term bf16 split), h = silu(u)*v
// 128 threads = 4 warps (2m x 2n), warp tile 64x32. CTA: 128 tokens x 32 h-cols.
// A via cp.async; B converted in-loop (reg prefetch). Hoisted B LDSM for both
// ks; MMAs in 3 passes per mt so same-acc RAW distance = 4.
// ---------------------------------------------------------------------------
__global__ void __launch_bounds__(128, 3) ffn1_kernel(const float* __restrict__ w1,
                                                      const float* __restrict__ w3) {
    const int e   = blockIdx.z;
    const int cnt = g_cnt[e];
    const int m0  = blockIdx.x * 128;
    if (m0 >= cnt) return;
    const int n0   = blockIdx.y * 32;     // h-cols
    const int base = g_off[e];

    extern __shared__ char sm[];
    const uint32_t sbase = smem_u32(sm);
    const int tid = threadIdx.x, lane = tid & 31, wid = tid >> 5;
    const int wm = wid & 1, wn = wid >> 1;

    const float* w1e = w1 + (size_t)e * DIM_ * HID_;
    const float* w3e = w3 + (size_t)e * DIM_ * HID_;

    // A loader: 1024 cp.async tasks (2 mats x 128 rows x 4 kq), 8/thread
    const __nv_bfloat16* apA[8];
    uint32_t aoA[8];
    #pragma unroll
    for (int q = 0; q < 8; q++) {
        int idx = tid + q * 128;
        int mat = idx >> 9;
        int rem = idx & 511;
        int row = rem >> 2, kq = rem & 3;
        int tok = g_list[e][min(m0 + row, cnt - 1)];
        apA[q] = (mat ? g_xlo : g_xhi) + (size_t)tok * DIM_ + kq * 8;
        aoA[q] = mat * TILE_A + row * ROWB + kq * 16;
    }
    // B loader: 256 tasks (64 interleaved rows x 4 k-blocks), 2/thread
    int bnT[2], bkT[2];
    const float* pB[2];
    #pragma unroll
    for (int r = 0; r < 2; r++) {
        int task = tid + r * 128;
        bnT[r] = task & 63;
        bkT[r] = task >> 6;
        pB[r]  = ((bnT[r] & 1) ? w3e : w1e) + (size_t)(bkT[r] * 8) * HID_ + (n0 + (bnT[r] >> 1));
    }

    const int mi = lane >> 3, lr = lane & 7;
    const uint32_t aLB = (uint32_t)((wm * 64 + (mi & 1) * 8 + lr) * ROWB + (mi >> 1) * 16);
    const uint32_t bLB = (uint32_t)((wn * 32 + (mi >> 1) * 8 + lr) * ROWB + (mi & 1) * 16);

    float acc[4][4][4];
    #pragma unroll
    for (int a = 0; a < 4; a++)
        #pragma unroll
        for (int b = 0; b < 4; b++)
            #pragma unroll
            for (int c = 0; c < 4; c++) acc[a][b][c] = 0.f;

    float pf[2][8];
    // ---- prologue: stage 0 ----
    #pragma unroll
    for (int q = 0; q < 8; q++) CP_ASYNC16(sbase + aoA[q], apA[q]);
    CP_COMMIT();
    #pragma unroll
    for (int r = 0; r < 2; r++)
        #pragma unroll
        for (int j = 0; j < 8; j++) pf[r][j] = pB[r][(size_t)j * HID_];
    #pragma unroll
    for (int r = 0; r < 2; r++) {
        uint32_t hp[4], lp[4];
        #pragma unroll
        for (int j = 0; j < 4; j++) split_pair(pf[r][2*j], pf[r][2*j+1], hp[j], lp[j]);
        uint32_t bo = bnT[r] * ROWB + bkT[r] * 16;
        *(uint4*)(sm + OFF_BH + bo) = make_uint4(hp[0], hp[1], hp[2], hp[3]);
        *(uint4*)(sm + OFF_BL + bo) = make_uint4(lp[0], lp[1], lp[2], lp[3]);
    }
    CP_WAIT0();
    __syncthreads();
    #pragma unroll
    for (int r = 0; r < 2; r++)
        #pragma unroll
        for (int j = 0; j < 8; j++) pf[r][j] = pB[r][(size_t)(32 + j) * HID_];

    const int NCH = DIM_ / 32;   // 64
    for (int i = 0; i < NCH; i++) {
        const uint32_t stS = sbase + (i & 1) * STAGE_B;
        // fill stage i+1 while computing stage i
        if (i + 1 < NCH) {
            const uint32_t stN = sbase + ((i + 1) & 1) * STAGE_B;
            char* stNc = sm + ((i + 1) & 1) * STAGE_B;
            int k0n = (i + 1) * 32;
            #pragma unroll
            for (int q = 0; q < 8; q++) CP_ASYNC16(stN + aoA[q], apA[q] + k0n);
            CP_COMMIT();
            #pragma unroll
            for (int r = 0; r < 2; r++) {
                uint32_t hp[4], lp[4];
                #pragma unroll
                for (int j = 0; j < 4; j++) split_pair(pf[r][2*j], pf[r][2*j+1], hp[j], lp[j]);
                uint32_t bo = bnT[r] * ROWB + bkT[r] * 16;
                *(uint4*)(stNc + OFF_BH + bo) = make_uint4(hp[0], hp[1], hp[2], hp[3]);
                *(uint4*)(stNc + OFF_BL + bo) = make_uint4(lp[0], lp[1], lp[2], lp[3]);
            }
        }
        if (i + 2 < NCH) {
            int k0p = (i + 2) * 32;
            #pragma unroll
            for (int r = 0; r < 2; r++)
                #pragma unroll
                for (int j = 0; j < 8; j++) pf[r][j] = pB[r][(size_t)(k0p + j) * HID_];
        }
        // ---- hoisted B loads for BOTH ks halfsteps ----
        uint32_t bh[2][2][4], bl[2][2][4];   // [ks][ng]
        #pragma unroll
        for (int ks = 0; ks < 2; ks++)
            #pragma unroll
            for (int ng = 0; ng < 2; ng++) {
                LDM_X4(bh[ks][ng], stS + OFF_BH + bLB + ng * (16 * ROWB) + ks * 32);
                LDM_X4(bl[ks][ng], stS + OFF_BL + bLB + ng * (16 * ROWB) + ks * 32);
            }
        // ---- compute ----
        #pragma unroll
        for (int ks = 0; ks < 2; ks++) {
            #pragma unroll
            for (int mt = 0; mt < 4; mt++) {
                uint32_t ah[4], al[4];
                LDM_X4(ah, stS + OFF_AH + aLB + mt * (16 * ROWB) + ks * 32);
                LDM_X4(al, stS + OFF_AL + aLB + mt * (16 * ROWB) + ks * 32);
                // pass 1: ah*bh  (same-acc RAW distance = 4)
                #pragma unroll
                for (int ng = 0; ng < 2; ng++)
                    #pragma unroll
                    for (int h2 = 0; h2 < 2; h2++)
                        MMA_BF16(acc[mt][ng*2+h2], ah, bh[ks][ng][2*h2], bh[ks][ng][2*h2+1]);
                // pass 2: al*bh
                #pragma unroll
                for (int ng = 0; ng < 2; ng++)
                    #pragma unroll
                    for (int h2 = 0; h2 < 2; h2++)
                        MMA_BF16(acc[mt][ng*2+h2], al, bh[ks][ng][2*h2], bh[ks][ng][2*h2+1]);
                // pass 3: ah*bl
                #pragma unroll
                for (int ng = 0; ng < 2; ng++)
                    #pragma unroll
                    for (int h2 = 0; h2 < 2; h2++)
                        MMA_BF16(acc[mt][ng*2+h2], ah, bl[ks][ng][2*h2], bl[ks][ng][2*h2+1]);
            }
        }
        CP_WAIT0();
        __syncthreads();
    }

    // epilogue: d0=u, d1=v for the same h-col, in-register SwiGLU
    #pragma unroll
    for (int mt = 0; mt < 4; mt++)
        #pragma unroll
        for (int nt = 0; nt < 4; nt++) {
            int j = wn * 16 + nt * 4 + (lane & 3);
            #pragma unroll
            for (int rr = 0; rr < 2; rr++) {
                int r  = wm * 64 + mt * 16 + (lane >> 2) + rr * 8;
                int gm = m0 + r;
                float u = acc[mt][nt][2*rr], v = acc[mt][nt][2*rr+1];
                float h = u / (1.f + __expf(-u)) * v;
                __nv_bfloat16 hh = __float2bfloat16(h);
                __nv_bfloat16 hl = __float2bfloat16(h - __bfloat162float(hh));
                if (gm < cnt) {
                    size_t dst = (size_t)(base + gm) * HID_ + n0 + j;
                    g_hh[dst] = hh;
                    g_hl[dst] = hl;
                }
            }
        }
}

// ---------------------------------------------------------------------------
// GEMM2: y = h @ w2 (3-term split). 128 threads, warp tile 64x32, CTA 128x64.
// Same hoisted-B + 3-pass MMA schedule.
// ---------------------------------------------------------------------------
__global__ void __launch_bounds__(128, 3) ffn2_kernel(const float* __restrict__ w2) {
    const int e   = blockIdx.z;
    const int cnt = g_cnt[e];
    const int m0  = blockIdx.x * 128;
    if (m0 >= cnt) return;
    const int n0   = blockIdx.y * 64;
    const int base = g_off[e];

    extern __shared__ char sm[];
    const uint32_t sbase = smem_u32(sm);
    const int tid = threadIdx.x, lane = tid & 31, wid = tid >> 5;
    const int wm = wid & 1, wn = wid >> 1;

    const float* w2e = w2 + (size_t)e * HID_ * DIM_;

    const __nv_bfloat16* apA[8];
    uint32_t aoA[8];
    #pragma unroll
    for (int q = 0; q < 8; q++) {
        int idx = tid + q * 128;
        int mat = idx >> 9;
        int rem = idx & 511;
        int row = rem >> 2, kq = rem & 3;
        int r   = base + min(m0 + row, cnt - 1);
        apA[q] = (mat ? g_hl : g_hh) + (size_t)r * HID_ + kq * 8;
        aoA[q] = mat * TILE_A + row * ROWB + kq * 16;
    }
    int bnT[2], bkT[2];
    const float* pB[2];
    #pragma unroll
    for (int r = 0; r < 2; r++) {
        int task = tid + r * 128;
        bnT[r] = task & 63;
        bkT[r] = task >> 6;
        pB[r]  = w2e + (size_t)(bkT[r] * 8) * DIM_ + (n0 + bnT[r]);
    }

    const int mi = lane >> 3, lr = lane & 7;
    const uint32_t aLB = (uint32_t)((wm * 64 + (mi & 1) * 8 + lr) * ROWB + (mi >> 1) * 16);
    const uint32_t bLB = (uint32_t)((wn * 32 + (mi >> 1) * 8 + lr) * ROWB + (mi & 1) * 16);

    float acc[4][4][4];
    #pragma unroll
    for (int a = 0; a < 4; a++)
        #pragma unroll
        for (int b = 0; b < 4; b++)
            #pragma unroll
            for (int c = 0; c < 4; c++) acc[a][b][c] = 0.f;

    float pf[2][8];
    #pragma unroll
    for (int q = 0; q < 8; q++) CP_ASYNC16(sbase + aoA[q], apA[q]);
    CP_COMMIT();
    #pragma unroll
    for (int r = 0; r < 2; r++)
        #pragma unroll
        for (int j = 0; j < 8; j++) pf[r][j] = pB[r][(size_t)j * DIM_];
    #pragma unroll
    for (int r = 0; r < 2; r++) {
        uint32_t hp[4], lp[4];
        #pragma unroll
        for (int j = 0; j < 4; j++) split_pair(pf[r][2*j], pf[r][2*j+1], hp[j], lp[j]);
        uint32_t bo = bnT[r] * ROWB + bkT[r] * 16;
        *(uint4*)(sm + OFF_BH + bo) = make_uint4(hp[0], hp[1], hp[2], hp[3]);
        *(uint4*)(sm + OFF_BL + bo) = make_uint4(lp[0], lp[1], lp[2], lp[3]);
    }
    CP_WAIT0();
    __syncthreads();
    #pragma unroll
    for (int r = 0; r < 2; r++)
        #pragma unroll
        for (int j = 0; j < 8; j++) pf[r][j] = pB[r][(size_t)(32 + j) * DIM_];

    const int NCH = HID_ / 32;   // 176
    for (int i = 0; i < NCH; i++) {
        const uint32_t stS = sbase + (i & 1) * STAGE_B;
        if (i + 1 < NCH) {
            const uint32_t stN = sbase + ((i + 1) & 1) * STAGE_B;
            char* stNc = sm + ((i + 1) & 1) * STAGE_B;
            int k0n = (i + 1) * 32;
            #pragma unroll
            for (int q = 0; q < 8; q++) CP_ASYNC16(stN + aoA[q], apA[q] + k0n);
            CP_COMMIT();
            #pragma unroll
            for (int r = 0; r < 2; r++) {
                uint32_t hp[4], lp[4];
                #pragma unroll
                for (int j = 0; j < 4; j++) split_pair(pf[r][2*j], pf[r][2*j+1], hp[j], lp[j]);
                uint32_t bo = bnT[r] * ROWB + bkT[r] * 16;
                *(uint4*)(stNc + OFF_BH + bo) = make_uint4(hp[0], hp[1], hp[2], hp[3]);
                *(uint4*)(stNc + OFF_BL + bo) = make_uint4(lp[0], lp[1], lp[2], lp[3]);
            }
        }
        if (i + 2 < NCH) {
            int k0p = (i + 2) * 32;
            #pragma unroll
            for (int r = 0; r < 2; r++)
                #pragma unroll
                for (int j = 0; j < 8; j++) pf[r][j] = pB[r][(size_t)(k0p + j) * DIM_];
        }
        uint32_t bh[2][2][4], bl[2][2][4];
        #pragma unroll
        for (int ks = 0; ks < 2; ks++)
            #pragma unroll
            for (int ng = 0; ng < 2; ng++) {
                LDM_X4(bh[ks][ng], stS + OFF_BH + bLB + ng * (16 * ROWB) + ks * 32);
                LDM_X4(bl[ks][ng], stS + OFF_BL + bLB + ng * (16 * ROWB) + ks * 32);
            }
        #pragma unroll
        for (int ks = 0; ks < 2; ks++) {
            #pragma unroll
            for (int mt = 0; mt < 4; mt++) {
                uint32_t ah[4], al[4];
                LDM_X4(ah, stS + OFF_AH + aLB + mt * (16 * ROWB) + ks * 32);
                LDM_X4(al, stS + OFF_AL + aLB + mt * (16 * ROWB) + ks * 32);
                #pragma unroll
                for (int ng = 0; ng < 2; ng++)
                    #pragma unroll
                    for (int h2 = 0; h2 < 2; h2++)
                        MMA_BF16(acc[mt][ng*2+h2], ah, bh[ks][ng][2*h2], bh[ks][ng][2*h2+1]);
                #pragma unroll
                for (int ng = 0; ng < 2; ng++)
                    #pragma unroll
                    for (int h2 = 0; h2 < 2; h2++)
                        MMA_BF16(acc[mt][ng*2+h2], al, bh[ks][ng][2*h2], bh[ks][ng][2*h2+1]);
                #pragma unroll
                for (int ng = 0; ng < 2; ng++)
                    #pragma unroll
                    for (int h2 = 0; h2 < 2; h2++)
                        MMA_BF16(acc[mt][ng*2+h2], ah, bl[ks][ng][2*h2], bl[ks][ng][2*h2+1]);
            }
        }
        CP_WAIT0();
        __syncthreads();
    }

    #pragma unroll
    for (int mt = 0; mt < 4; mt++)
        #pragma unroll
        for (int nt = 0; nt < 4; nt++) {
            int c = wn * 32 + nt * 8 + (lane & 3) * 2;
            #pragma unroll
            for (int rr = 0; rr < 2; rr++) {
                int r  = wm * 64 + mt * 16 + (lane >> 2) + rr * 8;
                int gm = m0 + r;
                if (gm < cnt) {
                    size_t dst = (size_t)(base + gm) * DIM_ + n0 + c;
                    *(float2*)(g_y + dst) = make_float2(acc[mt][nt][2*rr], acc[mt][nt][2*rr+1]);
                }
            }
        }
}

// ---------------------------------------------------------------------------
// Combine
// ---------------------------------------------------------------------------
__global__ void combine_kernel(float* __restrict__ out) {
    const int t  = blockIdx.x;
    const int e0 = g_eid[t][0];
    const int e1 = g_eid[t][1];
    const int n0 = g_off[e0] + g_pos[t][0];
    const int n1 = g_off[e1] + g_pos[t][1];
    const float w0 = g_ew[t][0];
    const float w1 = g_ew[t][1];
    const float* y0 = &g_y[(size_t)n0 * DIM_];
    const float* y1 = &g_y[(size_t)n1 * DIM_];
    float* op = out + (size_t)t * DIM_;
    for (int d = threadIdx.x * 4; d < DIM_; d += blockDim.x * 4) {
        float4 a = *(const float4*)(y0 + d);
        float4 b = *(const float4*)(y1 + d);
        *(float4*)(op + d) = make_float4(w0 * a.x + w1 * b.x, w0 * a.y + w1 * b.y,
                                         w0 * a.z + w1 * b.z, w0 * a.w + w1 * b.w);
    }
}

// ---------------------------------------------------------------------------
// Entry point
// ---------------------------------------------------------------------------
extern "C" void kernel_launch(void* const* d_in, const int* in_sizes, int n_in,
                              void* d_out, int out_size) {
    const float* x  = (const float*)d_in[0];
    const float* gw = (const float*)d_in[1];
    const float* w1 = (const float*)d_in[2];
    const float* w2 = (const float*)d_in[3];
    const float* w3 = (const float*)d_in[4];
    float* out = (float*)d_out;

    cudaFuncSetAttribute(ffn1_kernel, cudaFuncAttributeMaxDynamicSharedMemorySize, SMEM_TOT);
    cudaFuncSetAttribute(ffn2_kernel, cudaFuncAttributeMaxDynamicSharedMemorySize, SMEM_TOT);

    gate_kernel<<<T_TOKENS, 256>>>(x, gw);
    route_kernel<<<1, 256>>>();
    split_x_kernel<<<(T_TOKENS * DIM_ / 4) / 256, 256>>>(x);
    ffn1_kernel<<<dim3(T_TOKENS / 128, HID_ / 32, NEXP), 128, SMEM_TOT>>>(w1, w3);
    ffn2_kernel<<<dim3(T_TOKENS / 128, DIM_ / 64, NEXP), 128, SMEM_TOT>>>(w2);
    combine_kernel<<<T_TOKENS, 256>>>(out);
}

// round 9
// speedup vs baseline: 1.2063x; 1.0407x over previous
#include <cuda_runtime.h>
#include <cuda_bf16.h>
#include <cstdint>

#define T_TOKENS 2048
#define DIM_     2048
#define HID_     5632
#define NEXP     8
#define NENT     (T_TOKENS * 2)

// ---------------------------------------------------------------------------
// Scratch (device globals — no cudaMalloc allowed)
// ---------------------------------------------------------------------------
__device__ int   g_eid [T_TOKENS][2];
__device__ float g_ew  [T_TOKENS][2];
__device__ int   g_pos [T_TOKENS][2];
__device__ int   g_list[NEXP][T_TOKENS];
__device__ int   g_cnt [NEXP];
__device__ int   g_off [NEXP];
__device__ __nv_bfloat16 g_xhi[(size_t)T_TOKENS * DIM_];
__device__ __nv_bfloat16 g_xlo[(size_t)T_TOKENS * DIM_];
__device__ __nv_bfloat16 g_hh [(size_t)NENT * HID_];
__device__ __nv_bfloat16 g_hl [(size_t)NENT * HID_];
__device__ float         g_y  [(size_t)NENT * DIM_];

// ---------------------------------------------------------------------------
// Helpers
// ---------------------------------------------------------------------------
__device__ __forceinline__ uint32_t smem_u32(const void* p) {
    uint32_t a;
    asm("{ .reg .u64 t; cvta.to.shared.u64 t, %1; cvt.u32.u64 %0, t; }" : "=r"(a) : "l"(p));
    return a;
}
__device__ __forceinline__ uint32_t pkbf(__nv_bfloat16 a, __nv_bfloat16 b) {
    return (uint32_t)__bfloat16_as_ushort(a) | ((uint32_t)__bfloat16_as_ushort(b) << 16);
}
__device__ __forceinline__ void split_pair(float f0, float f1, uint32_t& hp, uint32_t& lp) {
    __nv_bfloat16 h0 = __float2bfloat16(f0);
    __nv_bfloat16 h1 = __float2bfloat16(f1);
    __nv_bfloat16 l0 = __float2bfloat16(f0 - __bfloat162float(h0));
    __nv_bfloat16 l1 = __float2bfloat16(f1 - __bfloat162float(h1));
    hp = pkbf(h0, h1);
    lp = pkbf(l0, l1);
}

#define LDM_X4(r, addr)                                                          \
    asm volatile("ldmatrix.sync.aligned.m8n8.x4.shared.b16 {%0,%1,%2,%3}, [%4];" \
        : "=r"((r)[0]), "=r"((r)[1]), "=r"((r)[2]), "=r"((r)[3]) : "r"(addr))

#define MMA_BF16(d, a, b0, b1)                                                   \
    asm volatile("mma.sync.aligned.m16n8k16.row.col.f32.bf16.bf16.f32 "          \
        "{%0,%1,%2,%3}, {%4,%5,%6,%7}, {%8,%9}, {%0,%1,%2,%3};"                  \
        : "+f"((d)[0]), "+f"((d)[1]), "+f"((d)[2]), "+f"((d)[3])                 \
        : "r"((a)[0]), "r"((a)[1]), "r"((a)[2]), "r"((a)[3]), "r"(b0), "r"(b1))

#define CP_ASYNC16(dst, src)                                                     \
    asm volatile("cp.async.cg.shared.global [%0], [%1], 16;" :: "r"(dst), "l"(src))
#define CP_COMMIT() asm volatile("cp.async.commit_group;" ::: "memory")
#define CP_WAIT0()  asm volatile("cp.async.wait_group 0;" ::: "memory")

// Smem geometry: rows of 32 bf16 padded to 80B -> conflict-free ldmatrix.
#define ROWB    80
#define TILE_A  10240           // 128 rows * 80B
#define OFF_AH  0
#define OFF_AL  10240
#define OFF_BH  20480           // B: 128 rows * 80B per matrix
#define OFF_BL  30720
#define STAGE_B 40960
#define SMEM_TOT (2 * STAGE_B)  // 81920; 2 CTAs/SM (163840 < 228KB)

// ---------------------------------------------------------------------------
// Gating + routing + x split
// ---------------------------------------------------------------------------
__global__ void gate_kernel(const float* __restrict__ x, const float* __restrict__ gw) {
    const int t = blockIdx.x, lane = threadIdx.x & 31, w = threadIdx.x >> 5;
    const float* xr = x + (size_t)t * DIM_;
    const float* gr = gw + (size_t)w * DIM_;
    float s = 0.f;
    for (int d = lane * 4; d < DIM_; d += 128) {
        float4 a = *(const float4*)(xr + d);
        float4 b = *(const float4*)(gr + d);
        s += a.x * b.x + a.y * b.y + a.z * b.z + a.w * b.w;
    }
    #pragma unroll
    for (int o = 16; o; o >>= 1) s += __shfl_xor_sync(0xffffffffu, s, o);
    __shared__ float sc[NEXP];
    if (lane == 0) sc[w] = s;
    __syncthreads();
    if (threadIdx.x == 0) {
        int b0 = 0; float s0 = sc[0];
        #pragma unroll
        for (int e = 1; e < NEXP; e++) if (sc[e] > s0) { s0 = sc[e]; b0 = e; }
        int b1 = -1; float s1 = -1e30f;
        #pragma unroll
        for (int e = 0; e < NEXP; e++) if (e != b0 && sc[e] > s1) { s1 = sc[e]; b1 = e; }
        float e1 = __expf(s1 - s0);
        float inv = 1.f / (1.f + e1);
        g_eid[t][0] = b0; g_eid[t][1] = b1;
        g_ew [t][0] = inv; g_ew [t][1] = e1 * inv;
    }
}

__global__ void route_kernel() {
    const int lane = threadIdx.x & 31, e = threadIdx.x >> 5;
    if (e < NEXP) {
        int cnt = 0;
        for (int t0 = 0; t0 < T_TOKENS; t0 += 32) {
            int t = t0 + lane;
            int e0 = g_eid[t][0], e1 = g_eid[t][1];
            bool sel = (e0 == e) || (e1 == e);
            int slot = (e0 == e) ? 0 : 1;
            unsigned m = __ballot_sync(0xffffffffu, sel);
            if (sel) {
                int p = cnt + __popc(m & ((1u << lane) - 1u));
                g_list[e][p] = t;
                g_pos[t][slot] = p;
            }
            cnt += __popc(m);
        }
        if (lane == 0) g_cnt[e] = cnt;
    }
    __syncthreads();
    if (threadIdx.x == 0) {
        int off = 0;
        #pragma unroll
        for (int i = 0; i < NEXP; i++) { g_off[i] = off; off += g_cnt[i]; }
    }
}

__global__ void split_x_kernel(const float* __restrict__ x) {
    int i = blockIdx.x * blockDim.x + threadIdx.x;
    float4 v = ((const float4*)x)[i];
    size_t o = (size_t)i * 4;
    float vv[4] = {v.x, v.y, v.z, v.w};
    #pragma unroll
    for (int k = 0; k < 4; k++) {
        __nv_bfloat16 h = __float2bfloat16(vv[k]);
        g_xhi[o + k] = h;
        g_xlo[o + k] = __float2bfloat16(vv[k] - __bfloat162float(h));
    }
}

// ---------------------------------------------------------------------------
// GEMM1: u = x@w1, v = x@w3 (3-term bf16 split), h = silu(u)*v
// 256 threads = 8 warps (2m x 4n), warp tile 64x32. CTA: 128 tokens x 64 h-cols
// (128 interleaved B rows). 2 CTAs/SM -> 16 warps/SM. A via cp.async; B
// converted in-loop (no reg prefetch; LDG latency hidden by extra warps).
// ---------------------------------------------------------------------------
__global__ void __launch_bounds__(256, 2) ffn1_kernel(const float* __restrict__ w1,
                                                      const float* __restrict__ w3) {
    const int e   = blockIdx.z;
    const int cnt = g_cnt[e];
    const int m0  = blockIdx.x * 128;
    if (m0 >= cnt) return;
    const int n0   = blockIdx.y * 64;     // h-cols
    const int base = g_off[e];

    extern __shared__ char sm[];
    const uint32_t sbase = smem_u32(sm);
    const int tid = threadIdx.x, lane = tid & 31, wid = tid >> 5;
    const int wm = wid & 1, wn = wid >> 1;

    const float* w1e = w1 + (size_t)e * DIM_ * HID_;
    const float* w3e = w3 + (size_t)e * DIM_ * HID_;

    // A loader: 1024 cp.async tasks (2 mats x 128 rows x 4 kq), 4/thread
    const __nv_bfloat16* apA[4];
    uint32_t aoA[4];
    #pragma unroll
    for (int q = 0; q < 4; q++) {
        int idx = tid + q * 256;
        int mat = idx >> 9;
        int rem = idx & 511;
        int row = rem >> 2, kq = rem & 3;
        int tok = g_list[e][min(m0 + row, cnt - 1)];
        apA[q] = (mat ? g_xlo : g_xhi) + (size_t)tok * DIM_ + kq * 8;
        aoA[q] = mat * TILE_A + row * ROWB + kq * 16;
    }
    // B loader: 512 tasks (128 interleaved rows x 4 k-blocks), 2/thread
    int bnT[2], bkT[2];
    const float* pB[2];
    #pragma unroll
    for (int r = 0; r < 2; r++) {
        int task = tid + r * 256;
        bnT[r] = task & 127;
        bkT[r] = task >> 7;
        pB[r]  = ((bnT[r] & 1) ? w3e : w1e) + (size_t)(bkT[r] * 8) * HID_ + (n0 + (bnT[r] >> 1));
    }

    const int mi = lane >> 3, lr = lane & 7;
    const uint32_t aLB = (uint32_t)((wm * 64 + (mi & 1) * 8 + lr) * ROWB + (mi >> 1) * 16);
    const uint32_t bLB = (uint32_t)((wn * 32 + (mi >> 1) * 8 + lr) * ROWB + (mi & 1) * 16);

    float acc[4][4][4];
    #pragma unroll
    for (int a = 0; a < 4; a++)
        #pragma unroll
        for (int b = 0; b < 4; b++)
            #pragma unroll
            for (int c = 0; c < 4; c++) acc[a][b][c] = 0.f;

    // ---- prologue: stage 0 ----
    #pragma unroll
    for (int q = 0; q < 4; q++) CP_ASYNC16(sbase + aoA[q], apA[q]);
    CP_COMMIT();
    #pragma unroll
    for (int r = 0; r < 2; r++) {
        float f[8];
        #pragma unroll
        for (int j = 0; j < 8; j++) f[j] = pB[r][(size_t)j * HID_];
        uint32_t hp[4], lp[4];
        #pragma unroll
        for (int j = 0; j < 4; j++) split_pair(f[2*j], f[2*j+1], hp[j], lp[j]);
        uint32_t bo = bnT[r] * ROWB + bkT[r] * 16;
        *(uint4*)(sm + OFF_BH + bo) = make_uint4(hp[0], hp[1], hp[2], hp[3]);
        *(uint4*)(sm + OFF_BL + bo) = make_uint4(lp[0], lp[1], lp[2], lp[3]);
    }
    CP_WAIT0();
    __syncthreads();

    const int NCH = DIM_ / 32;   // 64
    for (int i = 0; i < NCH; i++) {
        const uint32_t stS = sbase + (i & 1) * STAGE_B;
        // fill stage i+1 while computing stage i
        if (i + 1 < NCH) {
            const uint32_t stN = sbase + ((i + 1) & 1) * STAGE_B;
            char* stNc = sm + ((i + 1) & 1) * STAGE_B;
            int k0n = (i + 1) * 32;
            #pragma unroll
            for (int q = 0; q < 4; q++) CP_ASYNC16(stN + aoA[q], apA[q] + k0n);
            CP_COMMIT();
            #pragma unroll
            for (int r = 0; r < 2; r++) {
                float f[8];
                #pragma unroll
                for (int j = 0; j < 8; j++) f[j] = pB[r][(size_t)(k0n + j) * HID_];
                uint32_t hp[4], lp[4];
                #pragma unroll
                for (int j = 0; j < 4; j++) split_pair(f[2*j], f[2*j+1], hp[j], lp[j]);
                uint32_t bo = bnT[r] * ROWB + bkT[r] * 16;
                *(uint4*)(stNc + OFF_BH + bo) = make_uint4(hp[0], hp[1], hp[2], hp[3]);
                *(uint4*)(stNc + OFF_BL + bo) = make_uint4(lp[0], lp[1], lp[2], lp[3]);
            }
        }
        // compute stage i
        #pragma unroll
        for (int ks = 0; ks < 2; ks++) {
            uint32_t bh[2][4], bl[2][4];
            #pragma unroll
            for (int ng = 0; ng < 2; ng++) {
                LDM_X4(bh[ng], stS + OFF_BH + bLB + ng * (16 * ROWB) + ks * 32);
                LDM_X4(bl[ng], stS + OFF_BL + bLB + ng * (16 * ROWB) + ks * 32);
            }
            #pragma unroll
            for (int mt = 0; mt < 4; mt++) {
                uint32_t ah[4], al[4];
                LDM_X4(ah, stS + OFF_AH + aLB + mt * (16 * ROWB) + ks * 32);
                LDM_X4(al, stS + OFF_AL + aLB + mt * (16 * ROWB) + ks * 32);
                #pragma unroll
                for (int ng = 0; ng < 2; ng++)
                    #pragma unroll
                    for (int h2 = 0; h2 < 2; h2++) {
                        int nt = ng * 2 + h2;
                        MMA_BF16(acc[mt][nt], ah, bh[ng][2*h2], bh[ng][2*h2+1]);
                        MMA_BF16(acc[mt][nt], al, bh[ng][2*h2], bh[ng][2*h2+1]);
                        MMA_BF16(acc[mt][nt], ah, bl[ng][2*h2], bl[ng][2*h2+1]);
                    }
            }
        }
        CP_WAIT0();
        __syncthreads();
    }

    // epilogue: d0=u, d1=v for the same h-col, in-register SwiGLU
    #pragma unroll
    for (int mt = 0; mt < 4; mt++)
        #pragma unroll
        for (int nt = 0; nt < 4; nt++) {
            int j = wn * 16 + nt * 4 + (lane & 3);   // h-col within 64
            #pragma unroll
            for (int rr = 0; rr < 2; rr++) {
                int r  = wm * 64 + mt * 16 + (lane >> 2) + rr * 8;
                int gm = m0 + r;
                float u = acc[mt][nt][2*rr], v = acc[mt][nt][2*rr+1];
                float h = u / (1.f + __expf(-u)) * v;
                __nv_bfloat16 hh = __float2bfloat16(h);
                __nv_bfloat16 hl = __float2bfloat16(h - __bfloat162float(hh));
                if (gm < cnt) {
                    size_t dst = (size_t)(base + gm) * HID_ + n0 + j;
                    g_hh[dst] = hh;
                    g_hl[dst] = hl;
                }
            }
        }
}

// ---------------------------------------------------------------------------
// GEMM2: y = h @ w2 (3-term split). 256 threads (2m x 4n), CTA 128 x 128.
// ---------------------------------------------------------------------------
__global__ void __launch_bounds__(256, 2) ffn2_kernel(const float* __restrict__ w2) {
    const int e   = blockIdx.z;
    const int cnt = g_cnt[e];
    const int m0  = blockIdx.x * 128;
    if (m0 >= cnt) return;
    const int n0   = blockIdx.y * 128;
    const int base = g_off[e];

    extern __shared__ char sm[];
    const uint32_t sbase = smem_u32(sm);
    const int tid = threadIdx.x, lane = tid & 31, wid = tid >> 5;
    const int wm = wid & 1, wn = wid >> 1;

    const float* w2e = w2 + (size_t)e * HID_ * DIM_;

    const __nv_bfloat16* apA[4];
    uint32_t aoA[4];
    #pragma unroll
    for (int q = 0; q < 4; q++) {
        int idx = tid + q * 256;
        int mat = idx >> 9;
        int rem = idx & 511;
        int row = rem >> 2, kq = rem & 3;
        int r   = base + min(m0 + row, cnt - 1);
        apA[q] = (mat ? g_hl : g_hh) + (size_t)r * HID_ + kq * 8;
        aoA[q] = mat * TILE_A + row * ROWB + kq * 16;
    }
    int bnT[2], bkT[2];
    const float* pB[2];
    #pragma unroll
    for (int r = 0; r < 2; r++) {
        int task = tid + r * 256;
        bnT[r] = task & 127;
        bkT[r] = task >> 7;
        pB[r]  = w2e + (size_t)(bkT[r] * 8) * DIM_ + (n0 + bnT[r]);
    }

    const int mi = lane >> 3, lr = lane & 7;
    const uint32_t aLB = (uint32_t)((wm * 64 + (mi & 1) * 8 + lr) * ROWB + (mi >> 1) * 16);
    const uint32_t bLB = (uint32_t)((wn * 32 + (mi >> 1) * 8 + lr) * ROWB + (mi & 1) * 16);

    float acc[4][4][4];
    #pragma unroll
    for (int a = 0; a < 4; a++)
        #pragma unroll
        for (int b = 0; b < 4; b++)
            #pragma unroll
            for (int c = 0; c < 4; c++) acc[a][b][c] = 0.f;

    #pragma unroll
    for (int q = 0; q < 4; q++) CP_ASYNC16(sbase + aoA[q], apA[q]);
    CP_COMMIT();
    #pragma unroll
    for (int r = 0; r < 2; r++) {
        float f[8];
        #pragma unroll
        for (int j = 0; j < 8; j++) f[j] = pB[r][(size_t)j * DIM_];
        uint32_t hp[4], lp[4];
        #pragma unroll
        for (int j = 0; j < 4; j++) split_pair(f[2*j], f[2*j+1], hp[j], lp[j]);
        uint32_t bo = bnT[r] * ROWB + bkT[r] * 16;
        *(uint4*)(sm + OFF_BH + bo) = make_uint4(hp[0], hp[1], hp[2], hp[3]);
        *(uint4*)(sm + OFF_BL + bo) = make_uint4(lp[0], lp[1], lp[2], lp[3]);
    }
    CP_WAIT0();
    __syncthreads();

    const int NCH = HID_ / 32;   // 176
    for (int i = 0; i < NCH; i++) {
        const uint32_t stS = sbase + (i & 1) * STAGE_B;
        if (i + 1 < NCH) {
            const uint32_t stN = sbase + ((i + 1) & 1) * STAGE_B;
            char* stNc = sm + ((i + 1) & 1) * STAGE_B;
            int k0n = (i + 1) * 32;
            #pragma unroll
            for (int q = 0; q < 4; q++) CP_ASYNC16(stN + aoA[q], apA[q] + k0n);
            CP_COMMIT();
            #pragma unroll
            for (int r = 0; r < 2; r++) {
                float f[8];
                #pragma unroll
                for (int j = 0; j < 8; j++) f[j] = pB[r][(size_t)(k0n + j) * DIM_];
                uint32_t hp[4], lp[4];
                #pragma unroll
                for (int j = 0; j < 4; j++) split_pair(f[2*j], f[2*j+1], hp[j], lp[j]);
                uint32_t bo = bnT[r] * ROWB + bkT[r] * 16;
                *(uint4*)(stNc + OFF_BH + bo) = make_uint4(hp[0], hp[1], hp[2], hp[3]);
                *(uint4*)(stNc + OFF_BL + bo) = make_uint4(lp[0], lp[1], lp[2], lp[3]);
            }
        }
        #pragma unroll
        for (int ks = 0; ks < 2; ks++) {
            uint32_t bh[2][4], bl[2][4];
            #pragma unroll
            for (int ng = 0; ng < 2; ng++) {
                LDM_X4(bh[ng], stS + OFF_BH + bLB + ng * (16 * ROWB) + ks * 32);
                LDM_X4(bl[ng], stS + OFF_BL + bLB + ng * (16 * ROWB) + ks * 32);
            }
            #pragma unroll
            for (int mt = 0; mt < 4; mt++) {
                uint32_t ah[4], al[4];
                LDM_X4(ah, stS + OFF_AH + aLB + mt * (16 * ROWB) + ks * 32);
                LDM_X4(al, stS + OFF_AL + aLB + mt * (16 * ROWB) + ks * 32);
                #pragma unroll
                for (int ng = 0; ng < 2; ng++)
                    #pragma unroll
                    for (int h2 = 0; h2 < 2; h2++) {
                        int nt = ng * 2 + h2;
                        MMA_BF16(acc[mt][nt], ah, bh[ng][2*h2], bh[ng][2*h2+1]);
                        MMA_BF16(acc[mt][nt], al, bh[ng][2*h2], bh[ng][2*h2+1]);
                        MMA_BF16(acc[mt][nt], ah, bl[ng][2*h2], bl[ng][2*h2+1]);
                    }
            }
        }
        CP_WAIT0();
        __syncthreads();
    }

    #pragma unroll
    for (int mt = 0; mt < 4; mt++)
        #pragma unroll
        for (int nt = 0; nt < 4; nt++) {
            int c = wn * 32 + nt * 8 + (lane & 3) * 2;
            #pragma unroll
            for (int rr = 0; rr < 2; rr++) {
                int r  = wm * 64 + mt * 16 + (lane >> 2) + rr * 8;
                int gm = m0 + r;
                if (gm < cnt) {
                    size_t dst = (size_t)(base + gm) * DIM_ + n0 + c;
                    *(float2*)(g_y + dst) = make_float2(acc[mt][nt][2*rr], acc[mt][nt][2*rr+1]);
                }
            }
        }
}

// ---------------------------------------------------------------------------
// Combine
// ---------------------------------------------------------------------------
__global__ void combine_kernel(float* __restrict__ out) {
    const int t  = blockIdx.x;
    const int e0 = g_eid[t][0];
    const int e1 = g_eid[t][1];
    const int n0 = g_off[e0] + g_pos[t][0];
    const int n1 = g_off[e1] + g_pos[t][1];
    const float w0 = g_ew[t][0];
    const float w1 = g_ew[t][1];
    const float* y0 = &g_y[(size_t)n0 * DIM_];
    const float* y1 = &g_y[(size_t)n1 * DIM_];
    float* op = out + (size_t)t * DIM_;
    for (int d = threadIdx.x * 4; d < DIM_; d += blockDim.x * 4) {
        float4 a = *(const float4*)(y0 + d);
        float4 b = *(const float4*)(y1 + d);
        *(float4*)(op + d) = make_float4(w0 * a.x + w1 * b.x, w0 * a.y + w1 * b.y,
                                         w0 * a.z + w1 * b.z, w0 * a.w + w1 * b.w);
    }
}

// ---------------------------------------------------------------------------
// Entry point
// ---------------------------------------------------------------------------
extern "C" void kernel_launch(void* const* d_in, const int* in_sizes, int n_in,
                              void* d_out, int out_size) {
    const float* x  = (const float*)d_in[0];
    const float* gw = (const float*)d_in[1];
    const float* w1 = (const float*)d_in[2];
    const float* w2 = (const float*)d_in[3];
    const float* w3 = (const float*)d_in[4];
    float* out = (float*)d_out;

    cudaFuncSetAttribute(ffn1_kernel, cudaFuncAttributeMaxDynamicSharedMemorySize, SMEM_TOT);
    cudaFuncSetAttribute(ffn2_kernel, cudaFuncAttributeMaxDynamicSharedMemorySize, SMEM_TOT);

    gate_kernel<<<T_TOKENS, 256>>>(x, gw);
    route_kernel<<<1, 256>>>();
    split_x_kernel<<<(T_TOKENS * DIM_ / 4) / 256, 256>>>(x);
    ffn1_kernel<<<dim3(T_TOKENS / 128, HID_ / 64, NEXP), 256, SMEM_TOT>>>(w1, w3);
    ffn2_kernel<<<dim3(T_TOKENS / 128, DIM_ / 128, NEXP), 256, SMEM_TOT>>>(w2);
    combine_kernel<<<T_TOKENS, 256>>>(out);
}